// round 15
// baseline (speedup 1.0000x reference)
#include <cuda_runtime.h>
#include <math.h>

#define SELF_DIM  36
#define OTHER_DIM 28
#define OTHER_NUM 19
#define OBS_DIM   568            // 36 + 28*19
#define ROW_BYTES (OBS_DIM * 4)  // 2272
#define HID       64
#define NW        6              // warps per block
#define RPW       8              // rows per warp per group
#define RPG       (NW * RPW)     // 48

// Dynamic smem layout (bytes)
#define SMEM_M    0                       // packed M: 64*64 f32 = 16384
#define SMEM_PV   16384                   // NW*RPW*64 f32 = 12288
#define SMEM_SX   28672                   // NW*2*568 f32 = 27264
#define SMEM_C    55936                   // 64 f32
#define SMEM_W    56192                   // 28 f32
#define SMEM_MB   56320                   // NW*2 u64 = 96
#define SMEM_CTR  56416                   // 2 ints
#define SMEM_TOTAL 56448

// Scratch (allocation-free)
__device__ __align__(16) float g_M[64 * 64];
__device__ __align__(16) float g_c[64];
__device__ __align__(16) float g_w[OTHER_DIM];
__device__ int g_ctr;

// ---------------------------------------------------------------------------
// Fused-weight precompute (65 blocks x 256 threads; 4-way K split + reduce):
//   M'[k][h] = (We @ Wo[:64])[k][h] + (k<36 ? ((Ws[:36]+Ws[36:]) @ Wo[64:])[k][h] : 0)
//   c[h]     = bo[h] + be @ Wo[:64] + bs @ Wo[64:]
//   w[d]     = Wa[36+d]   (self logit part + ba are softmax-invariant)
// Also resets the dynamic-work counter (deterministic across graph replays).
// ---------------------------------------------------------------------------
__global__ void precompute_kernel(const float* __restrict__ Wa,
                                  const float* __restrict__ We,
                                  const float* __restrict__ be,
                                  const float* __restrict__ Ws,
                                  const float* __restrict__ bs,
                                  const float* __restrict__ Wo,
                                  const float* __restrict__ bo) {
    __shared__ float red[256];
    const int h    = threadIdx.x & 63;
    const int part = threadIdx.x >> 6;      // 0..3
    const int j0   = part * 16;

    if (blockIdx.x < 64) {
        const int k = blockIdx.x;
        float acc = 0.f;
        #pragma unroll 4
        for (int j = j0; j < j0 + 16; j++)
            acc += We[k * HID + j] * Wo[j * HID + h];
        if (k < SELF_DIM) {
            #pragma unroll 4
            for (int j = j0; j < j0 + 16; j++)
                acc += (Ws[k * HID + j] + Ws[(k + SELF_DIM) * HID + j]) * Wo[(64 + j) * HID + h];
        }
        red[threadIdx.x] = acc;
        __syncthreads();
        if (part == 0)
            g_M[k * HID + h] = red[h] + red[64 + h] + red[128 + h] + red[192 + h];
    } else {
        float cc = 0.f;
        #pragma unroll 4
        for (int j = j0; j < j0 + 16; j++)
            cc += be[j] * Wo[j * HID + h] + bs[j] * Wo[(64 + j) * HID + h];
        red[threadIdx.x] = cc;
        __syncthreads();
        if (part == 0)
            g_c[h] = bo[h] + red[h] + red[64 + h] + red[128 + h] + red[192 + h];
        if (threadIdx.x < OTHER_DIM) g_w[threadIdx.x] = Wa[SELF_DIM + threadIdx.x];
        if (threadIdx.x == 0) g_ctr = 0;
    }
}

// ---------------------------------------------------------------------------
// Packed fp32x2 helpers (Blackwell SIMD fp32; PTX-only)
// ---------------------------------------------------------------------------
typedef unsigned long long u64;

__device__ __forceinline__ u64 pk2(float x, float y) {
    u64 u; asm("mov.b64 %0, {%1, %2};" : "=l"(u) : "f"(x), "f"(y)); return u;
}
__device__ __forceinline__ float2 upk2(u64 u) {
    float2 f; asm("mov.b64 {%0, %1}, %2;" : "=f"(f.x), "=f"(f.y) : "l"(u)); return f;
}
__device__ __forceinline__ u64 ffma2(u64 a, u64 b, u64 c) {
    u64 d; asm("fma.rn.f32x2 %0, %1, %2, %3;" : "=l"(d) : "l"(a), "l"(b), "l"(c)); return d;
}
__device__ __forceinline__ unsigned sptr(const void* p) {
    return (unsigned)__cvta_generic_to_shared(p);
}

// ---------------------------------------------------------------------------
// Main kernel. Persistent blocks (4/SM), dynamic 48-row-group stealing.
// Per warp: rows double-buffer-staged via cp.async.bulk, conflict-free rotated
// logit loads, max-free softmax, pooling, then 8-row f32x2 GEMM with
// 2x2-packed M (ld.shared.v2.u64).
//
// Packed-M layout: float4 #((k>>1)*32 + (h>>1)) holds
//   { M[k][h], M[k][h+1], M[k+1][h], M[k+1][h+1] }   (k,h even)
// 32 h-pairs per k-pair row -> stride 32 float4s (512 B) per k-pair.
// ---------------------------------------------------------------------------
__global__ void __launch_bounds__(NW * 32, 4)
gat_kernel(const float* __restrict__ x, float* __restrict__ out,
           int nrows, int ngroups) {
    extern __shared__ __align__(16) unsigned char dsm[];
    float* Msh  = (float*)(dsm + SMEM_M);
    float* pvb  = (float*)(dsm + SMEM_PV);
    float* sxb  = (float*)(dsm + SMEM_SX);
    float* csh  = (float*)(dsm + SMEM_C);
    float* wsh  = (float*)(dsm + SMEM_W);
    u64*   mbs  = (u64*)  (dsm + SMEM_MB);
    int*   sctr = (int*)  (dsm + SMEM_CTR);

    const int tid  = threadIdx.x;
    const int warp = tid >> 5;
    const int lane = tid & 31;

    // Pack M into smem (stride 32 float4s per k-pair — fits exactly in 16 KB)
    for (int i = tid; i < 64 * 64; i += NW * 32) {
        int k = i >> 6, h = i & 63;
        float v = g_M[i];
        Msh[((((k >> 1) << 5) + (h >> 1)) << 2) + ((k & 1) << 1) + (h & 1)] = v;
    }
    if (tid < 64)                          csh[tid]      = g_c[tid];
    if (tid >= 64 && tid < 64 + OTHER_DIM) wsh[tid - 64] = g_w[tid - 64];
    if (tid < NW * 2) {
        unsigned a = sptr(mbs + tid);
        asm volatile("mbarrier.init.shared.b64 [%0], 1;" :: "r"(a) : "memory");
    }
    if (tid == 0) {
        sctr[0] = atomicAdd(&g_ctr, 1);
        sctr[1] = atomicAdd(&g_ctr, 1);
    }
    asm volatile("fence.proxy.async.shared::cta;" ::: "memory");
    __syncthreads();

    float* sxw = sxb + warp * (2 * OBS_DIM);
    float* pvw = pvb + warp * (RPW * HID);
    const unsigned mb0 = sptr(mbs + warp * 2);
    const unsigned mb1 = sptr(mbs + warp * 2 + 1);
    const unsigned msh_sa = sptr(Msh);
    const int rot = (lane >> 3) << 1;   // de-conflicts lanes i / i+8 / i+16

    // async bulk copy of one row into buffer b
    auto issue = [&](int row, int b) {
        if (row < nrows && lane == 0) {
            unsigned mb  = b ? mb1 : mb0;
            unsigned dst = sptr(sxw + b * OBS_DIM);
            const float* src = x + (size_t)row * OBS_DIM;
            int nbytes = ROW_BYTES;
            asm volatile("mbarrier.arrive.expect_tx.shared.b64 _, [%0], %1;"
                         :: "r"(mb), "r"(nbytes) : "memory");
            asm volatile("cp.async.bulk.shared::cluster.global.mbarrier::complete_tx::bytes "
                         "[%0], [%1], %2, [%3];"
                         :: "r"(dst), "l"(src), "r"(nbytes), "r"(mb) : "memory");
        }
    };

    int cur = sctr[0];
    int nxt = sctr[1];

    issue(cur * RPG + warp * RPW + 0, 0);
    issue(cur * RPG + warp * RPW + 1, 1);
    int ph0 = 0, ph1 = 0;

    while (cur < ngroups) {
        const int rbase = cur * RPG + warp * RPW;

        #pragma unroll 1
        for (int j = 0; j < RPW; j++) {
            const int row = rbase + j;
            if (row >= nrows) continue;            // warp-uniform
            const int b = j & 1;
            const unsigned mb = b ? mb1 : mb0;
            const int par = b ? (ph1++ & 1) : (ph0++ & 1);

            asm volatile(
                "{\n\t.reg .pred P;\n"
                "LW%=:\n\t"
                "mbarrier.try_wait.parity.acquire.cta.shared::cta.b64 P, [%0], %1, 0x989680;\n\t"
                "@!P bra LW%=;\n\t}"
                :: "r"(mb), "r"(par) : "memory");

            const float* sb = sxw + b * OBS_DIM;

            // ---- logits (lane i = slot i), rotated chunk order ----
            float e;
            if (lane < OTHER_NUM) {
                const float* o = sb + SELF_DIM + lane * OTHER_DIM;
                float acc = 0.f;
                #pragma unroll
                for (int s = 0; s < 7; s++) {
                    int c = s + rot; c = (c >= 7) ? c - 7 : c;
                    float4 ov = *(const float4*)(o + (c << 2));
                    float4 wv = *(const float4*)(wsh + (c << 2));
                    acc += ov.x * wv.x + ov.y * wv.y + ov.z * wv.z + ov.w * wv.w;
                }
                e = __expf(acc);    // max-free: |logit| bounded, exp safe
            } else {
                e = 0.f;
            }
            float sm = e;
            #pragma unroll
            for (int off = 16; off > 0; off >>= 1)
                sm += __shfl_xor_sync(0xffffffffu, sm, off);
            const float inv = 1.f / sm;

            // ---- pooling: lane d sums e_i * others[i][d], normalize once ----
            const int dl = (lane < OTHER_DIM) ? lane : 0;
            float p = 0.f;
            #pragma unroll
            for (int i = 0; i < OTHER_NUM; i++) {
                float a = __shfl_sync(0xffffffffu, e, i);
                p += a * sb[SELF_DIM + i * OTHER_DIM + dl];
            }
            float* pr = pvw + j * HID;
            if (lane < OTHER_DIM) pr[SELF_DIM + lane] = p * inv;
            pr[lane] = sb[lane];
            if (lane < SELF_DIM - 32) pr[32 + lane] = sb[32 + lane];
            __syncwarp();           // buffer fully consumed

            // refill this buffer: slot j+2 (crosses into next group at j=6,7)
            int irow;
            if (j < RPW - 2)        irow = rbase + j + 2;
            else if (nxt < ngroups) irow = nxt * RPG + warp * RPW + (j - (RPW - 2));
            else                    irow = nrows;   // no-op
            issue(irow, b);
        }

        // ---- 8-row register-blocked GEMM: out = pv @ M' + c (f32x2, packed M) ----
        u64 acc[RPW];
        {
            float2 ci = *(const float2*)(csh + 2 * lane);
            u64 c0 = pk2(ci.x, ci.y);
            #pragma unroll
            for (int j = 0; j < RPW; j++) acc[j] = c0;
        }
        #pragma unroll
        for (int k0 = 0; k0 < 64; k0 += 4) {
            float4 qv[RPW];
            #pragma unroll
            for (int j = 0; j < RPW; j++)
                qv[j] = *(const float4*)(pvw + j * HID + k0);

            // k-pair (k0,k0+1) at float4 #((k0>>1)*32 + lane); next pair +32 float4s
            unsigned ma = msh_sa + ((((k0 >> 1) << 5) + lane) << 4);
            u64 m0, m1, m2, m3;
            asm("ld.shared.v2.u64 {%0, %1}, [%2];" : "=l"(m0), "=l"(m1) : "r"(ma));
            asm("ld.shared.v2.u64 {%0, %1}, [%2];" : "=l"(m2), "=l"(m3) : "r"(ma + (32 << 4)));

            #pragma unroll
            for (int j = 0; j < RPW; j++) {
                acc[j] = ffma2(pk2(qv[j].x, qv[j].x), m0, acc[j]);
                acc[j] = ffma2(pk2(qv[j].y, qv[j].y), m1, acc[j]);
                acc[j] = ffma2(pk2(qv[j].z, qv[j].z), m2, acc[j]);
                acc[j] = ffma2(pk2(qv[j].w, qv[j].w), m3, acc[j]);
            }
        }
        #pragma unroll
        for (int j = 0; j < RPW; j++) {
            const int row = rbase + j;
            if (row < nrows)
                *(float2*)(out + (size_t)row * HID + 2 * lane) = upk2(acc[j]);
        }

        // ---- steal next group (one bar per 48 rows) ----
        if (tid == 0) sctr[1] = atomicAdd(&g_ctr, 1);
        __syncthreads();
        cur = nxt;
        nxt = sctr[1];
    }
}

// ---------------------------------------------------------------------------
extern "C" void kernel_launch(void* const* d_in, const int* in_sizes, int n_in,
                              void* d_out, int out_size) {
    const float* x  = (const float*)d_in[0];
    const float* Wa = (const float*)d_in[1];
    // d_in[2] = ba : softmax-invariant, unused
    const float* We = (const float*)d_in[3];
    const float* be = (const float*)d_in[4];
    const float* Ws = (const float*)d_in[5];
    const float* bs = (const float*)d_in[6];
    const float* Wo = (const float*)d_in[7];
    const float* bo = (const float*)d_in[8];
    float* out = (float*)d_out;

    const int nrows = in_sizes[0] / OBS_DIM;

    cudaFuncSetAttribute(gat_kernel, cudaFuncAttributeMaxDynamicSharedMemorySize,
                         SMEM_TOTAL);

    precompute_kernel<<<65, 256>>>(Wa, We, be, Ws, bs, Wo, bo);

    const int ngroups = (nrows + RPG - 1) / RPG;
    int grid = 148 * 4;                 // persistent, exactly 4 blocks/SM
    if (grid > ngroups) grid = ngroups;
    gat_kernel<<<grid, NW * 32, SMEM_TOTAL>>>(x, out, nrows, ngroups);
}